// round 15
// baseline (speedup 1.0000x reference)
#include <cuda_runtime.h>
#include <cuda_bf16.h>

#define LL 512
#define DD 512
#define HH 512

typedef unsigned long long ull;

// ---------------- device scratch ----------------
__device__ float g_u[LL * DD];
__device__ float g_w[LL * DD];
__device__ float g_e[LL * LL];
__device__ float g_a[LL * LL];
__device__ float g_c[LL * DD];
__device__ float g_gi_f[LL * 3 * HH];
__device__ float g_gi_b[LL * 3 * HH];
__device__ float g_h[2][2][HH];               // fallback: [dir][parity][h]
__device__ unsigned int g_flag[2][32][32];    // fallback: per-producer flag lines
// dataflow flags (release-add counters)
__device__ unsigned int g_uwflag[2][8];       // [u|w][64-row block] -> 8
__device__ unsigned int g_givflag[2][8];      // head gi v-half [dir][m-block] -> 24
__device__ unsigned int g_gicflag[2][8];      // tail gi final  [dir][m-block] -> 24

__device__ __forceinline__ float sigm_(float x) {
    return __fdividef(1.f, 1.f + __expf(-x));
}
__device__ __forceinline__ float tanh_(float x) {
    return 1.f - __fdividef(2.f, __expf(x + x) + 1.f);
}
__device__ __forceinline__ unsigned int ld_acq(const unsigned int* p) {
    unsigned int v;
    asm volatile("ld.acquire.gpu.global.u32 %0, [%1];" : "=r"(v) : "l"(p) : "memory");
    return v;
}
__device__ __forceinline__ void st_rel(unsigned int* p, unsigned int v) {
    asm volatile("st.release.gpu.global.u32 [%0], %1;" :: "l"(p), "r"(v) : "memory");
}
__device__ __forceinline__ void red_add_rel(unsigned int* p) {
    asm volatile("red.release.gpu.global.add.u32 [%0], %1;" :: "l"(p), "r"(1u) : "memory");
}
__device__ __forceinline__ void trigger_dependents() {
    asm volatile("griddepcontrol.launch_dependents;" ::: "memory");
}
__device__ __forceinline__ void ffma2(ull& d, ull a, ull b) {
    asm("fma.rn.f32x2 %0, %1, %2, %0;" : "+l"(d) : "l"(a), "l"(b));
}
__device__ __forceinline__ void addx2(ull& d, ull a) {
    asm("add.rn.f32x2 %0, %0, %1;" : "+l"(d) : "l"(a));
}
__device__ __forceinline__ ull packff(float x) {
    ull r; asm("mov.b64 %0, {%1, %1};" : "=l"(r) : "f"(x)); return r;
}
__device__ __forceinline__ ull pack2(float x, float y) {
    ull r; asm("mov.b64 %0, {%1, %2};" : "=l"(r) : "f"(x), "f"(y)); return r;
}
__device__ __forceinline__ float2 unpk(ull v) {
    float2 f; asm("mov.b64 {%0, %1}, %2;" : "=f"(f.x), "=f"(f.y) : "l"(v)); return f;
}
__device__ __forceinline__ unsigned smem_u32(const void* p) {
    unsigned a;
    asm("{ .reg .u64 t; cvta.to.shared.u64 t, %1; cvt.u32.u64 %0, t; }" : "=r"(a) : "l"(p));
    return a;
}
__device__ __forceinline__ unsigned ctarank_() {
    unsigned r; asm("mov.u32 %0, %%cluster_ctarank;" : "=r"(r)); return r;
}
__device__ __forceinline__ void mbar_wait(unsigned addr, unsigned parity) {
    asm volatile(
        "{\n\t"
        ".reg .pred P;\n\t"
        "WL_%=:\n\t"
        "mbarrier.try_wait.parity.acquire.cta.shared::cta.b64 P, [%0], %1, 0x989680;\n\t"
        "@!P bra WL_%=;\n\t"
        "}"
        :: "r"(addr), "r"(parity) : "memory");
}
__device__ __forceinline__ void mbar_rearm(unsigned addr, unsigned bytes) {
    asm volatile("mbarrier.arrive.expect_tx.shared.b64 _, [%0], %1;"
                 :: "r"(addr), "r"(bytes) : "memory");
}
// warp-converged acquire spin (all lanes)
__device__ __forceinline__ void warp_wait_flag(const unsigned* p, unsigned target) {
    while (__any_sync(0xffffffffu, ld_acq(p) < target)) {}
}

// ---------------- init (flags + fallback state) ----------------
__global__ void init_zero() {
    int i = blockIdx.x * 1024 + threadIdx.x;
    if (i < 2048) ((unsigned int*)g_flag)[i] = 0u;
    if (i < 2048) ((float*)g_h)[i] = 0.f;
    if (blockIdx.x == 0 && threadIdx.x < 16) {
        ((unsigned int*)g_uwflag)[threadIdx.x] = 0u;
        ((unsigned int*)g_givflag)[threadIdx.x] = 0u;
        ((unsigned int*)g_gicflag)[threadIdx.x] = 0u;
    }
}

// ---------------- GEMM core (f32x2 packed, explicit m0/n0) ----------------
__device__ __forceinline__ void gemm_core(
    const float* __restrict__ A, int lda,
    const float* __restrict__ B, int ldb,
    const float* __restrict__ bias, float* __restrict__ C,
    int N, int Kloop, int transB, int accum, int m0, int n0)
{
    __shared__ __align__(16) float As[16][68];
    __shared__ __align__(16) float Bs[16][68];
    const int tid = threadIdx.x;
    const int tm = (tid >> 4) * 4, tn = (tid & 15) * 4;
    ull acc[4][2] = {};
    for (int k0 = 0; k0 < Kloop; k0 += 16) {
#pragma unroll
        for (int i = 0; i < 4; i++) {
            int e = tid + 256 * i;
            {
                int kk = e & 15, row = e >> 4;
                As[kk][row] = A[(size_t)(m0 + row) * lda + k0 + kk];
            }
            if (transB) {
                int kk = e & 15, row = e >> 4;
                Bs[kk][row] = B[(size_t)(n0 + row) * ldb + k0 + kk];
            } else {
                int n = e & 63, kk = e >> 6;
                Bs[kk][n] = B[(size_t)(k0 + kk) * ldb + n0 + n];
            }
        }
        __syncthreads();
#pragma unroll
        for (int kk = 0; kk < 16; kk++) {
            float4 a = *(const float4*)&As[kk][tm];
            const ull* bp = (const ull*)&Bs[kk][tn];
            ull b01 = bp[0], b23 = bp[1];
            ull a0 = packff(a.x), a1 = packff(a.y), a2 = packff(a.z), a3 = packff(a.w);
            ffma2(acc[0][0], a0, b01); ffma2(acc[0][1], a0, b23);
            ffma2(acc[1][0], a1, b01); ffma2(acc[1][1], a1, b23);
            ffma2(acc[2][0], a2, b01); ffma2(acc[2][1], a2, b23);
            ffma2(acc[3][0], a3, b01); ffma2(acc[3][1], a3, b23);
        }
        __syncthreads();
    }
#pragma unroll
    for (int i = 0; i < 4; i++) {
        float2 c01 = unpk(acc[i][0]), c23 = unpk(acc[i][1]);
        float* cp = C + (size_t)(m0 + tm + i) * N + n0 + tn;
        float b0 = 0.f, b1 = 0.f, b2 = 0.f, b3 = 0.f;
        if (bias) { b0 = bias[n0+tn]; b1 = bias[n0+tn+1]; b2 = bias[n0+tn+2]; b3 = bias[n0+tn+3]; }
        if (accum) { b0 += cp[0]; b1 += cp[1]; b2 += cp[2]; b3 += cp[3]; }
        cp[0] = c01.x + b0; cp[1] = c01.y + b1; cp[2] = c23.x + b2; cp[3] = c23.y + b3;
    }
}

// head: z=0 -> u, z=1 -> w (8x8), z=2/3 -> gi v-half (24x8). Triggers PDL + flags.
__global__ void gemm_head(const float* __restrict__ v,
                          const float* __restrict__ w1, const float* __restrict__ b1,
                          const float* __restrict__ w2, const float* __restrict__ b2,
                          const float* __restrict__ wih_f, const float* __restrict__ bih_f,
                          const float* __restrict__ wih_b, const float* __restrict__ bih_b) {
    trigger_dependents();
    const int z = blockIdx.z;
    const int m0 = blockIdx.y * 64, n0 = blockIdx.x * 64;
    if (z < 2) {
        if (blockIdx.x >= 8) return;
        if (z == 0) gemm_core(v, 512, w1, 512, b1, g_u, 512, 512, 1, 0, m0, n0);
        else        gemm_core(v, 512, w2, 512, b2, g_w, 512, 512, 1, 0, m0, n0);
        __syncthreads();
        if (threadIdx.x == 0) red_add_rel(&g_uwflag[z][blockIdx.y]);
    } else {
        if (z == 2) gemm_core(v, 512, wih_f, 1024, bih_f, g_gi_f, 1536, 512, 1, 0, m0, n0);
        else        gemm_core(v, 512, wih_b, 1024, bih_b, g_gi_b, 1536, 512, 1, 0, m0, n0);
        __syncthreads();
        if (threadIdx.x == 0) red_add_rel(&g_givflag[z - 2][blockIdx.y]);
    }
}

// c = a @ v, 32x64 tiles
__global__ void gemm_c32(const float* __restrict__ v) {
    __shared__ __align__(16) float As[16][36];
    __shared__ __align__(16) float Bs[16][68];
    const int tid = threadIdx.x;
    const int m0 = blockIdx.y * 32, n0 = blockIdx.x * 64;
    const int tm = (tid >> 4) * 2, tn = (tid & 15) * 4;
    ull acc[2][2] = {};
    for (int k0 = 0; k0 < 512; k0 += 16) {
#pragma unroll
        for (int i = 0; i < 2; i++) {
            int e = tid + 256 * i;
            int kk = e & 15, row = e >> 4;
            As[kk][row] = g_a[(size_t)(m0 + row) * 512 + k0 + kk];
        }
#pragma unroll
        for (int i = 0; i < 4; i++) {
            int e = tid + 256 * i;
            int n = e & 63, kk = e >> 6;
            Bs[kk][n] = v[(size_t)(k0 + kk) * 512 + n0 + n];
        }
        __syncthreads();
#pragma unroll
        for (int kk = 0; kk < 16; kk++) {
            float2 a2 = *(const float2*)&As[kk][tm];
            const ull* bp = (const ull*)&Bs[kk][tn];
            ull b01 = bp[0], b23 = bp[1];
            ull a0 = packff(a2.x), a1 = packff(a2.y);
            ffma2(acc[0][0], a0, b01); ffma2(acc[0][1], a0, b23);
            ffma2(acc[1][0], a1, b01); ffma2(acc[1][1], a1, b23);
        }
        __syncthreads();
    }
#pragma unroll
    for (int i = 0; i < 2; i++) {
        float2 c01 = unpk(acc[i][0]), c23 = unpk(acc[i][1]);
        float* cp = g_c + (size_t)(m0 + tm + i) * 512 + n0 + tn;
        cp[0] = c01.x; cp[1] = c01.y; cp[2] = c23.x; cp[3] = c23.y;
    }
}

// tail: gi += c @ wih[:,512:]^T ; z=1 runs m-blocks in reverse t order; flags.
__global__ void gemm_tail(const float* __restrict__ wih_f, const float* __restrict__ wih_b) {
    trigger_dependents();
    const int z = blockIdx.z;
    const int my = z ? (7 - blockIdx.y) : blockIdx.y;
    if (threadIdx.x == 0)
        while (ld_acq(&g_givflag[z][my]) < 24u) {}
    __syncthreads();
    const int m0 = my * 64, n0 = blockIdx.x * 64;
    if (z == 0) gemm_core(g_c, 512, wih_f + 512, 1024, nullptr, g_gi_f, 1536, 512, 1, 1, m0, n0);
    else        gemm_core(g_c, 512, wih_b + 512, 1024, nullptr, g_gi_b, 1536, 512, 1, 1, m0, n0);
    __syncthreads();
    if (threadIdx.x == 0) red_add_rel(&g_gicflag[z][my]);
}

// ---------------- attn e (PDL secondary, flag-gated) ----------------
__global__ void attn_e(const float* __restrict__ v) {
    __shared__ float us[32][33], vs[32][33], ws[16][33];
    const int tx = threadIdx.x, ty = threadIdx.y;
    const int j0 = blockIdx.x * 32, t0 = blockIdx.y * 16;
    if (tx == 0 && ty == 0) {
        while (ld_acq(&g_uwflag[0][blockIdx.x >> 1]) < 8u) {}
        while (ld_acq(&g_uwflag[1][blockIdx.y >> 2]) < 8u) {}
    }
    __syncthreads();
    float acc = 0.f;
    for (int d0 = 0; d0 < DD; d0 += 32) {
        us[ty][tx]      = g_u[(j0 + ty) * DD + d0 + tx];
        us[ty + 16][tx] = g_u[(j0 + ty + 16) * DD + d0 + tx];
        vs[ty][tx]      = v[(j0 + ty) * DD + d0 + tx];
        vs[ty + 16][tx] = v[(j0 + ty + 16) * DD + d0 + tx];
        ws[ty][tx]      = g_w[(t0 + ty) * DD + d0 + tx];
        __syncthreads();
#pragma unroll
        for (int dd = 0; dd < 32; dd++) {
            float x = us[tx][dd] + ws[ty][dd];
            float th = 1.f - __fdividef(2.f, __expf(x + x) + 1.f);
            acc = fmaf(th, vs[tx][dd], acc);
        }
        __syncthreads();
    }
    g_e[(t0 + ty) * LL + j0 + tx] = acc;
    // drain head completely before this kernel retires (orders stream successors)
    if (tx == 0 && ty == 0) {
#pragma unroll
        for (int d = 0; d < 2; d++)
#pragma unroll
            for (int m = 0; m < 8; m++)
                while (ld_acq(&g_givflag[d][m]) < 24u) {}
    }
}

// ---------------- softmax rows ----------------
__global__ void softmax_rows() {
    __shared__ float red[16];
    __shared__ float bval;
    const int t = blockIdx.x, tid = threadIdx.x, w = tid >> 5, l = tid & 31;
    float x = g_e[t * LL + tid];
    float m = x;
#pragma unroll
    for (int o = 16; o; o >>= 1) m = fmaxf(m, __shfl_xor_sync(~0u, m, o));
    if (l == 0) red[w] = m;
    __syncthreads();
    if (tid == 0) {
        float mm = red[0];
#pragma unroll
        for (int i = 1; i < 16; i++) mm = fmaxf(mm, red[i]);
        bval = mm;
    }
    __syncthreads();
    float p = __expf(x - bval);
    float s = p;
#pragma unroll
    for (int o = 16; o; o >>= 1) s += __shfl_xor_sync(~0u, s, o);
    if (l == 0) red[w] = s;
    __syncthreads();
    if (tid == 0) {
        float ss = red[0];
#pragma unroll
        for (int i = 1; i < 16; i++) ss += red[i];
        bval = ss;
    }
    __syncthreads();
    g_a[t * LL + tid] = __fdividef(p, bval);
}

// ======== GRU scan: 16-CTA cluster, 4-chunk st.async, PDL behind tail ========
__global__ void __launch_bounds__(512, 1) gru_cluster(
    const float* __restrict__ whh_f, const float* __restrict__ bhh_f,
    const float* __restrict__ whh_b, const float* __restrict__ bhh_b,
    float* __restrict__ out)
{
    __shared__ __align__(16) float hbuf[2][HH];
    __shared__ __align__(8) ull mbC[4][2];
    const int dir = blockIdx.x >> 4;
    const int wrp = threadIdx.x >> 5, lane = threadIdx.x & 31;
    const unsigned rank = ctarank_();
    const int j0 = (int)rank * 32 + wrp * 2;
    const int half = lane >> 4;
    const int jh = j0 + half;
    const float* whh = dir ? whh_b : whh_f;
    const float* bhh = dir ? bhh_b : bhh_f;
    const float* gi  = dir ? g_gi_b : g_gi_f;
    const unsigned* gicf = g_gicflag[dir];
    float* outp = out + dir * HH;

    ull wt[3][16];
#pragma unroll
    for (int g = 0; g < 3; g++) {
        const float* r0 = whh + ((size_t)(g * HH + j0)) * HH;
        const float* r1 = r0 + HH;
#pragma unroll
        for (int i = 0; i < 16; i++) {
            int k = lane + 32 * i;
            wt[g][i] = pack2(r0[k], r1[k]);
        }
    }
    const float bRs = bhh[jh], bZs = bhh[HH + jh], bNs = bhh[2 * HH + jh];

    for (int i = threadIdx.x; i < HH; i += 512) hbuf[0][i] = 0.f;
    const unsigned sb0 = smem_u32(&hbuf[0][0]);
    const unsigned sb1 = smem_u32(&hbuf[1][0]);
    const unsigned mbc = smem_u32(&mbC[0][0]);
    if (threadIdx.x == 0) {
#pragma unroll
        for (int q = 0; q < 8; q++) {
            asm volatile("mbarrier.init.shared.b64 [%0], %1;"
                         :: "r"(mbc + q * 8u), "r"(1u) : "memory");
            mbar_rearm(mbc + q * 8u, 512u);
        }
    }
    __syncthreads();
    asm volatile("barrier.cluster.arrive.aligned;" ::: "memory");
    asm volatile("barrier.cluster.wait.aligned;" ::: "memory");

    // gi prefetch for step 0 (flag-gated per warp)
    float giR, giZ, giN;
    {
        const int t0 = dir ? (LL - 1) : 0;
        warp_wait_flag(&gicf[t0 >> 6], 24u);
        const float* gt = gi + (size_t)t0 * (3 * HH);
        giR = __ldg(gt + jh); giZ = __ldg(gt + HH + jh); giN = __ldg(gt + 2 * HH + jh);
    }

    unsigned parbits = 0u;
    for (int s = 0; s < LL; s++) {
        const int t = dir ? (LL - 1 - s) : s;
        float nxR = 0.f, nxZ = 0.f, nxN = 0.f;
        if (s + 1 < LL) {
            const int tn_ = dir ? (LL - 2 - s) : (s + 1);
            if (dir ? ((tn_ & 63) == 63) : ((tn_ & 63) == 0))
                warp_wait_flag(&gicf[tn_ >> 6], 24u);
            const float* gt = gi + (size_t)tn_ * (3 * HH);
            nxR = __ldg(gt + jh); nxZ = __ldg(gt + HH + jh); nxN = __ldg(gt + 2 * HH + jh);
        }
        const int sl = s & 1;
        const float* hp = hbuf[sl];
        ull aR = 0, aZ = 0, aN = 0;
#pragma unroll
        for (int c = 0; c < 4; c++) {
            if (s > 0) {
                const unsigned idx = (unsigned)(c * 2 + sl);
                const unsigned ma = mbc + idx * 8u;
                mbar_wait(ma, (parbits >> idx) & 1u);
                parbits ^= (1u << idx);
                if (threadIdx.x == 0) mbar_rearm(ma, 512u);
            }
#pragma unroll
            for (int i = 4 * c; i < 4 * c + 4; i++) {
                ull hh = packff(hp[lane + 32 * i]);
                ffma2(aR, wt[0][i], hh); ffma2(aZ, wt[1][i], hh); ffma2(aN, wt[2][i], hh);
            }
        }
#pragma unroll
        for (int o = 16; o; o >>= 1) {
            ull tR = __shfl_xor_sync(0xffffffffu, aR, o);
            ull tZ = __shfl_xor_sync(0xffffffffu, aZ, o);
            ull tN = __shfl_xor_sync(0xffffffffu, aN, o);
            addx2(aR, tR); addx2(aZ, tZ); addx2(aN, tN);
        }
        float2 fR = unpk(aR), fZ = unpk(aZ), fN = unpk(aN);
        float aRs = half ? fR.y : fR.x;
        float aZs = half ? fZ.y : fZ.x;
        float aNs = half ? fN.y : fN.x;
        float rr = sigm_(giR + aRs + bRs);
        float zz = sigm_(giZ + aZs + bZs);
        float nn = tanh_(giN + rr * (aNs + bNs));
        float hprev = hp[jh];
        float hv = (1.f - zz) * nn + zz * hprev;
        float hov = __shfl_xor_sync(0xffffffffu, hv, 16);
        if (s + 1 < LL && lane < 16) {
            ull pairv = pack2(hv, hov);
            const int nsl = (s + 1) & 1;
            unsigned ldata = (nsl ? sb1 : sb0) + (unsigned)j0 * 4u;
            unsigned lmbar = mbc + (unsigned)((rank >> 2) * 2 + nsl) * 8u;
            unsigned rdata, rmbar;
            asm("mapa.shared::cluster.u32 %0, %1, %2;" : "=r"(rdata) : "r"(ldata), "r"(lane));
            asm("mapa.shared::cluster.u32 %0, %1, %2;" : "=r"(rmbar) : "r"(lmbar), "r"(lane));
            asm volatile("st.async.shared::cluster.mbarrier::complete_tx::bytes.b64 [%0], %1, [%2];"
                         :: "r"(rdata), "l"(pairv), "r"(rmbar) : "memory");
        }
        if (lane == 0) *(float2*)&outp[(size_t)t * (2 * HH) + j0] = make_float2(hv, hov);
        giR = nxR; giZ = nxZ; giN = nxN;
    }
    asm volatile("barrier.cluster.arrive.aligned;" ::: "memory");
    asm volatile("barrier.cluster.wait.aligned;" ::: "memory");
}

// ---------------- fallback GRU (R3, global-flag sync) ----------------
__global__ void __launch_bounds__(512, 1) gru_flags(
    const float* __restrict__ whh_f, const float* __restrict__ bhh_f,
    const float* __restrict__ whh_b, const float* __restrict__ bhh_b,
    float* __restrict__ out)
{
    const int dir = blockIdx.x >> 5, cta = blockIdx.x & 31;
    const int wrp = threadIdx.x >> 5, lane = threadIdx.x & 31;
    const int j = cta * 16 + wrp;
    const float* whh = dir ? whh_b : whh_f;
    const float* bhh = dir ? bhh_b : bhh_f;
    const float* gi  = dir ? g_gi_b : g_gi_f;

    float wr[16], wz[16], wn[16];
#pragma unroll
    for (int i = 0; i < 16; i++) {
        int k = lane + 32 * i;
        wr[i] = whh[(size_t)j * HH + k];
        wz[i] = whh[(size_t)(HH + j) * HH + k];
        wn[i] = whh[(size_t)(2 * HH + j) * HH + k];
    }
    const float bhr = bhh[j], bhz = bhh[HH + j], bhn = bhh[2 * HH + j];

    for (int s = 0; s < LL; s++) {
        const int t = dir ? (LL - 1 - s) : s;
        float giR = 0.f, giZ = 0.f, giN = 0.f;
        if (lane == 0) {
            const float* gt = gi + (size_t)t * (3 * HH);
            giR = __ldg(&gt[j]); giZ = __ldg(&gt[HH + j]); giN = __ldg(&gt[2 * HH + j]);
        }
        if (s > 0 && wrp == 0) {
            const unsigned tgt = (unsigned)s;
            while (__any_sync(0xffffffffu, ld_acq(&g_flag[dir][lane][0]) < tgt)) {}
        }
        __syncthreads();
        const float* hp = g_h[dir][s & 1];
        float* hn = g_h[dir][(s + 1) & 1];
        float aR = 0.f, aZ = 0.f, aN = 0.f;
#pragma unroll
        for (int i = 0; i < 16; i++) {
            float hv = __ldcg(&hp[lane + 32 * i]);
            aR = fmaf(wr[i], hv, aR);
            aZ = fmaf(wz[i], hv, aZ);
            aN = fmaf(wn[i], hv, aN);
        }
#pragma unroll
        for (int o = 16; o; o >>= 1) {
            aR += __shfl_xor_sync(0xffffffffu, aR, o);
            aZ += __shfl_xor_sync(0xffffffffu, aZ, o);
            aN += __shfl_xor_sync(0xffffffffu, aN, o);
        }
        if (lane == 0) {
            float r = sigm_(giR + aR + bhr);
            float z = sigm_(giZ + aZ + bhz);
            float n = tanh_(giN + r * (aN + bhn));
            float hprev = __ldcg(&hp[j]);
            float hnew = (1.f - z) * n + z * hprev;
            __stcg(&hn[j], hnew);
            out[(size_t)t * (2 * HH) + dir * HH + j] = hnew;
        }
        __syncthreads();
        if (threadIdx.x == 0) st_rel(&g_flag[dir][cta][0], (unsigned)(s + 1));
    }
}

// ---------------- launch ----------------
extern "C" void kernel_launch(void* const* d_in, const int* in_sizes, int n_in,
                              void* d_out, int out_size) {
    const float* v     = (const float*)d_in[0];
    const float* w1    = (const float*)d_in[1];
    const float* b1    = (const float*)d_in[2];
    const float* w2    = (const float*)d_in[3];
    const float* b2    = (const float*)d_in[4];
    const float* wih_f = (const float*)d_in[5];
    const float* whh_f = (const float*)d_in[6];
    const float* bih_f = (const float*)d_in[7];
    const float* bhh_f = (const float*)d_in[8];
    const float* wih_b = (const float*)d_in[9];
    const float* whh_b = (const float*)d_in[10];
    const float* bih_b = (const float*)d_in[11];
    const float* bhh_b = (const float*)d_in[12];
    float* out = (float*)d_out;

    // cluster feasibility (query with cluster attr only)
    cudaFuncSetAttribute((const void*)gru_cluster,
                         cudaFuncAttributeNonPortableClusterSizeAllowed, 1);
    cudaLaunchConfig_t qcfg = {};
    qcfg.gridDim = dim3(32, 1, 1);
    qcfg.blockDim = dim3(512, 1, 1);
    cudaLaunchAttribute qattr[1];
    qattr[0].id = cudaLaunchAttributeClusterDimension;
    qattr[0].val.clusterDim = {16, 1, 1};
    qcfg.attrs = qattr;
    qcfg.numAttrs = 1;
    int nclus = 0;
    cudaError_t qe = cudaOccupancyMaxActiveClusters(&nclus, gru_cluster, &qcfg);
    bool use_cluster = (qe == cudaSuccess && nclus >= 2);
    if (!use_cluster) cudaGetLastError();

    init_zero<<<2, 1024>>>();
    gemm_head<<<dim3(24, 8, 4), 256>>>(v, w1, b1, w2, b2,
                                       wih_f, bih_f, wih_b, bih_b);

    // attn with PDL (overlaps head); fallback to normal launch on error
    {
        cudaLaunchConfig_t acfg = {};
        acfg.gridDim = dim3(16, 32, 1);
        acfg.blockDim = dim3(32, 16, 1);
        cudaLaunchAttribute aattr[1];
        aattr[0].id = cudaLaunchAttributeProgrammaticStreamSerialization;
        aattr[0].val.programmaticStreamSerializationAllowed = 1;
        acfg.attrs = aattr;
        acfg.numAttrs = 1;
        cudaError_t ae = cudaLaunchKernelEx(&acfg, attn_e, v);
        if (ae != cudaSuccess) {
            cudaGetLastError();
            attn_e<<<dim3(16, 32), dim3(32, 16)>>>(v);
        }
    }
    softmax_rows<<<512, 512>>>();
    gemm_c32<<<dim3(8, 16), 256>>>(v);
    gemm_tail<<<dim3(24, 8, 2), 256>>>(wih_f, wih_b);

    if (use_cluster) {
        cudaLaunchConfig_t cfg = {};
        cfg.gridDim = dim3(32, 1, 1);
        cfg.blockDim = dim3(512, 1, 1);
        cudaLaunchAttribute attrs[2];
        attrs[0].id = cudaLaunchAttributeClusterDimension;
        attrs[0].val.clusterDim = {16, 1, 1};
        attrs[1].id = cudaLaunchAttributeProgrammaticStreamSerialization;
        attrs[1].val.programmaticStreamSerializationAllowed = 1;
        cfg.attrs = attrs;
        cfg.numAttrs = 2;
        cudaError_t le = cudaLaunchKernelEx(&cfg, gru_cluster,
                                            whh_f, bhh_f, whh_b, bhh_b, out);
        if (le != cudaSuccess) {
            cudaGetLastError();
            // retry without PDL
            cfg.numAttrs = 1;
            le = cudaLaunchKernelEx(&cfg, gru_cluster,
                                    whh_f, bhh_f, whh_b, bhh_b, out);
            if (le != cudaSuccess) {
                cudaGetLastError();
                gru_flags<<<64, 512>>>(whh_f, bhh_f, whh_b, bhh_b, out);
            }
        }
    } else {
        gru_flags<<<64, 512>>>(whh_f, bhh_f, whh_b, bhh_b, out);
    }
}

// round 16
// speedup vs baseline: 1.0758x; 1.0758x over previous
#include <cuda_runtime.h>
#include <cuda_bf16.h>

#define LL 512
#define DD 512
#define HH 512

typedef unsigned long long ull;

// ---------------- device scratch ----------------
__device__ float g_u[LL * DD];
__device__ float g_w[LL * DD];
__device__ float g_e[LL * LL];
__device__ float g_a[LL * LL];
__device__ float g_c[LL * DD];
__device__ float g_gi_f[LL * 3 * HH];
__device__ float g_gi_b[LL * 3 * HH];
__device__ float g_h[2][2][HH];               // fallback: [dir][parity][h]
__device__ unsigned int g_flag[2][32][32];    // fallback: per-producer flag lines

__device__ __forceinline__ float sigm_(float x) {
    return __fdividef(1.f, 1.f + __expf(-x));
}
__device__ __forceinline__ float tanh_(float x) {
    return 1.f - __fdividef(2.f, __expf(x + x) + 1.f);
}
__device__ __forceinline__ unsigned int ld_acq(const unsigned int* p) {
    unsigned int v;
    asm volatile("ld.acquire.gpu.global.u32 %0, [%1];" : "=r"(v) : "l"(p) : "memory");
    return v;
}
__device__ __forceinline__ void st_rel(unsigned int* p, unsigned int v) {
    asm volatile("st.release.gpu.global.u32 [%0], %1;" :: "l"(p), "r"(v) : "memory");
}
__device__ __forceinline__ void ffma2(ull& d, ull a, ull b) {
    asm("fma.rn.f32x2 %0, %1, %2, %0;" : "+l"(d) : "l"(a), "l"(b));
}
__device__ __forceinline__ void addx2(ull& d, ull a) {
    asm("add.rn.f32x2 %0, %0, %1;" : "+l"(d) : "l"(a));
}
__device__ __forceinline__ ull packff(float x) {
    ull r; asm("mov.b64 %0, {%1, %1};" : "=l"(r) : "f"(x)); return r;
}
__device__ __forceinline__ ull pack2(float x, float y) {
    ull r; asm("mov.b64 %0, {%1, %2};" : "=l"(r) : "f"(x), "f"(y)); return r;
}
__device__ __forceinline__ float2 unpk(ull v) {
    float2 f; asm("mov.b64 {%0, %1}, %2;" : "=f"(f.x), "=f"(f.y) : "l"(v)); return f;
}
__device__ __forceinline__ unsigned smem_u32(const void* p) {
    unsigned a;
    asm("{ .reg .u64 t; cvta.to.shared.u64 t, %1; cvt.u32.u64 %0, t; }" : "=r"(a) : "l"(p));
    return a;
}
__device__ __forceinline__ unsigned ctarank_() {
    unsigned r; asm("mov.u32 %0, %%cluster_ctarank;" : "=r"(r)); return r;
}
__device__ __forceinline__ void mbar_wait(unsigned addr, unsigned parity) {
    asm volatile(
        "{\n\t"
        ".reg .pred P;\n\t"
        "WL_%=:\n\t"
        "mbarrier.try_wait.parity.acquire.cta.shared::cta.b64 P, [%0], %1, 0x989680;\n\t"
        "@!P bra WL_%=;\n\t"
        "}"
        :: "r"(addr), "r"(parity) : "memory");
}
__device__ __forceinline__ void mbar_rearm(unsigned addr, unsigned bytes) {
    asm volatile("mbarrier.arrive.expect_tx.shared.b64 _, [%0], %1;"
                 :: "r"(addr), "r"(bytes) : "memory");
}

// ---------------- init (fallback path only) ----------------
__global__ void init_zero() {
    int i = blockIdx.x * 1024 + threadIdx.x;
    if (i < 2048) ((unsigned int*)g_flag)[i] = 0u;
    if (i < 2048) ((float*)g_h)[i] = 0.f;
}

// ---------------- GEMM core (f32x2 packed, lda/ldb/accum generalized) ----------------
__device__ __forceinline__ void gemm_core(
    const float* __restrict__ A, int lda,
    const float* __restrict__ B, int ldb,
    const float* __restrict__ bias, float* __restrict__ C,
    int N, int Kloop, int transB, int accum, int m0, int n0)
{
    __shared__ __align__(16) float As[16][68];
    __shared__ __align__(16) float Bs[16][68];
    const int tid = threadIdx.x;
    const int tm = (tid >> 4) * 4, tn = (tid & 15) * 4;
    ull acc[4][2] = {};
    for (int k0 = 0; k0 < Kloop; k0 += 16) {
#pragma unroll
        for (int i = 0; i < 4; i++) {
            int e = tid + 256 * i;
            {
                int kk = e & 15, row = e >> 4;
                As[kk][row] = A[(size_t)(m0 + row) * lda + k0 + kk];
            }
            if (transB) {
                int kk = e & 15, row = e >> 4;
                Bs[kk][row] = B[(size_t)(n0 + row) * ldb + k0 + kk];
            } else {
                int n = e & 63, kk = e >> 6;
                Bs[kk][n] = B[(size_t)(k0 + kk) * ldb + n0 + n];
            }
        }
        __syncthreads();
#pragma unroll
        for (int kk = 0; kk < 16; kk++) {
            float4 a = *(const float4*)&As[kk][tm];
            const ull* bp = (const ull*)&Bs[kk][tn];
            ull b01 = bp[0], b23 = bp[1];
            ull a0 = packff(a.x), a1 = packff(a.y), a2 = packff(a.z), a3 = packff(a.w);
            ffma2(acc[0][0], a0, b01); ffma2(acc[0][1], a0, b23);
            ffma2(acc[1][0], a1, b01); ffma2(acc[1][1], a1, b23);
            ffma2(acc[2][0], a2, b01); ffma2(acc[2][1], a2, b23);
            ffma2(acc[3][0], a3, b01); ffma2(acc[3][1], a3, b23);
        }
        __syncthreads();
    }
#pragma unroll
    for (int i = 0; i < 4; i++) {
        float2 c01 = unpk(acc[i][0]), c23 = unpk(acc[i][1]);
        float* cp = C + (size_t)(m0 + tm + i) * N + n0 + tn;
        float b0 = 0.f, b1 = 0.f, b2 = 0.f, b3 = 0.f;
        if (bias) { b0 = bias[n0+tn]; b1 = bias[n0+tn+1]; b2 = bias[n0+tn+2]; b3 = bias[n0+tn+3]; }
        if (accum) { b0 += cp[0]; b1 += cp[1]; b2 += cp[2]; b3 += cp[3]; }
        cp[0] = c01.x + b0; cp[1] = c01.y + b1; cp[2] = c23.x + b2; cp[3] = c23.y + b3;
    }
}

// head: z=0 -> u, z=1 -> w (8x8 blocks), z=2/3 -> gi v-half (24x8)
__global__ void gemm_head(const float* __restrict__ v,
                          const float* __restrict__ w1, const float* __restrict__ b1,
                          const float* __restrict__ w2, const float* __restrict__ b2,
                          const float* __restrict__ wih_f, const float* __restrict__ bih_f,
                          const float* __restrict__ wih_b, const float* __restrict__ bih_b) {
    const int z = blockIdx.z;
    const int m0 = blockIdx.y * 64, n0 = blockIdx.x * 64;
    if (z < 2) {
        if (blockIdx.x >= 8) return;
        if (z == 0) gemm_core(v, 512, w1, 512, b1, g_u, 512, 512, 1, 0, m0, n0);
        else        gemm_core(v, 512, w2, 512, b2, g_w, 512, 512, 1, 0, m0, n0);
    } else {
        if (z == 2) gemm_core(v, 512, wih_f, 1024, bih_f, g_gi_f, 1536, 512, 1, 0, m0, n0);
        else        gemm_core(v, 512, wih_b, 1024, bih_b, g_gi_b, 1536, 512, 1, 0, m0, n0);
    }
}
// c = a @ v with 32x64 tiles
__global__ void gemm_c32(const float* __restrict__ v) {
    __shared__ __align__(16) float As[16][36];
    __shared__ __align__(16) float Bs[16][68];
    const int tid = threadIdx.x;
    const int m0 = blockIdx.y * 32, n0 = blockIdx.x * 64;
    const int tm = (tid >> 4) * 2, tn = (tid & 15) * 4;
    ull acc[2][2] = {};
    for (int k0 = 0; k0 < 512; k0 += 16) {
#pragma unroll
        for (int i = 0; i < 2; i++) {
            int e = tid + 256 * i;
            int kk = e & 15, row = e >> 4;
            As[kk][row] = g_a[(size_t)(m0 + row) * 512 + k0 + kk];
        }
#pragma unroll
        for (int i = 0; i < 4; i++) {
            int e = tid + 256 * i;
            int n = e & 63, kk = e >> 6;
            Bs[kk][n] = v[(size_t)(k0 + kk) * 512 + n0 + n];
        }
        __syncthreads();
#pragma unroll
        for (int kk = 0; kk < 16; kk++) {
            float2 a2 = *(const float2*)&As[kk][tm];
            const ull* bp = (const ull*)&Bs[kk][tn];
            ull b01 = bp[0], b23 = bp[1];
            ull a0 = packff(a2.x), a1 = packff(a2.y);
            ffma2(acc[0][0], a0, b01); ffma2(acc[0][1], a0, b23);
            ffma2(acc[1][0], a1, b01); ffma2(acc[1][1], a1, b23);
        }
        __syncthreads();
    }
#pragma unroll
    for (int i = 0; i < 2; i++) {
        float2 c01 = unpk(acc[i][0]), c23 = unpk(acc[i][1]);
        float* cp = g_c + (size_t)(m0 + tm + i) * 512 + n0 + tn;
        cp[0] = c01.x; cp[1] = c01.y; cp[2] = c23.x; cp[3] = c23.y;
    }
}
__global__ void gemm_tail(const float* __restrict__ wih_f, const float* __restrict__ wih_b) {
    const int m0 = blockIdx.y * 64, n0 = blockIdx.x * 64;
    if (blockIdx.z == 0) gemm_core(g_c, 512, wih_f + 512, 1024, nullptr, g_gi_f, 1536, 512, 1, 1, m0, n0);
    else                 gemm_core(g_c, 512, wih_b + 512, 1024, nullptr, g_gi_b, 1536, 512, 1, 1, m0, n0);
}

// ---------------- attn e ----------------
__global__ void attn_e(const float* __restrict__ v) {
    __shared__ float us[32][33], vs[32][33], ws[16][33];
    const int tx = threadIdx.x, ty = threadIdx.y;
    const int j0 = blockIdx.x * 32, t0 = blockIdx.y * 16;
    float acc = 0.f;
    for (int d0 = 0; d0 < DD; d0 += 32) {
        us[ty][tx]      = g_u[(j0 + ty) * DD + d0 + tx];
        us[ty + 16][tx] = g_u[(j0 + ty + 16) * DD + d0 + tx];
        vs[ty][tx]      = v[(j0 + ty) * DD + d0 + tx];
        vs[ty + 16][tx] = v[(j0 + ty + 16) * DD + d0 + tx];
        ws[ty][tx]      = g_w[(t0 + ty) * DD + d0 + tx];
        __syncthreads();
#pragma unroll
        for (int dd = 0; dd < 32; dd++) {
            float x = us[tx][dd] + ws[ty][dd];
            float th = 1.f - __fdividef(2.f, __expf(x + x) + 1.f);
            acc = fmaf(th, vs[tx][dd], acc);
        }
        __syncthreads();
    }
    g_e[(t0 + ty) * LL + j0 + tx] = acc;
}

// ---------------- softmax rows ----------------
__global__ void softmax_rows() {
    __shared__ float red[16];
    __shared__ float bval;
    const int t = blockIdx.x, tid = threadIdx.x, w = tid >> 5, l = tid & 31;
    float x = g_e[t * LL + tid];
    float m = x;
#pragma unroll
    for (int o = 16; o; o >>= 1) m = fmaxf(m, __shfl_xor_sync(~0u, m, o));
    if (l == 0) red[w] = m;
    __syncthreads();
    if (tid == 0) {
        float mm = red[0];
#pragma unroll
        for (int i = 1; i < 16; i++) mm = fmaxf(mm, red[i]);
        bval = mm;
    }
    __syncthreads();
    float p = __expf(x - bval);
    float s = p;
#pragma unroll
    for (int o = 16; o; o >>= 1) s += __shfl_xor_sync(~0u, s, o);
    if (l == 0) red[w] = s;
    __syncthreads();
    if (tid == 0) {
        float ss = red[0];
#pragma unroll
        for (int i = 1; i < 16; i++) ss += red[i];
        bval = ss;
    }
    __syncthreads();
    g_a[t * LL + tid] = __fdividef(p, bval);
}

// ======== GRU scan: 16-CTA cluster, 4-chunk st.async, pair-load matvec ========
// h consumed as 8 LDS.64 pairs per thread (pair p = lane+32*i -> h[2p],h[2p+1]);
// accumulators packed (k-even, k-odd) per row: 6 accs, no packff movs.
// Chunk c = source ranks 4c..4c+3 = pairs [64c,64c+64) -> i in {2c, 2c+1}.
__global__ void __launch_bounds__(512, 1) gru_cluster(
    const float* __restrict__ whh_f, const float* __restrict__ bhh_f,
    const float* __restrict__ whh_b, const float* __restrict__ bhh_b,
    float* __restrict__ out)
{
    __shared__ __align__(16) float hbuf[2][HH];
    __shared__ __align__(8) ull mbC[4][2];
    const int dir = blockIdx.x >> 4;
    const int wrp = threadIdx.x >> 5, lane = threadIdx.x & 31;
    const unsigned rank = ctarank_();
    const int j0 = (int)rank * 32 + wrp * 2;
    const int half = lane >> 4;          // 0 -> row j0, 1 -> row j0+1
    const int jh = j0 + half;
    const float* whh = dir ? whh_b : whh_f;
    const float* bhh = dir ? bhh_b : bhh_f;
    const float* gi  = dir ? g_gi_b : g_gi_f;
    float* outp = out + dir * HH;

    // weights: wt[g*2+r][i] = (w_{j0+r, 2p}, w_{j0+r, 2p+1}), p = lane + 32*i
    ull wt[6][8];
#pragma unroll
    for (int g = 0; g < 3; g++) {
#pragma unroll
        for (int r = 0; r < 2; r++) {
            const float* row = whh + ((size_t)(g * HH + j0 + r)) * HH;
#pragma unroll
            for (int i = 0; i < 8; i++) {
                int p = lane + 32 * i;
                wt[g * 2 + r][i] = pack2(row[2 * p], row[2 * p + 1]);
            }
        }
    }
    const float bRs = bhh[jh], bZs = bhh[HH + jh], bNs = bhh[2 * HH + jh];

    for (int i = threadIdx.x; i < HH; i += 512) hbuf[0][i] = 0.f;
    const unsigned sb0 = smem_u32(&hbuf[0][0]);
    const unsigned sb1 = smem_u32(&hbuf[1][0]);
    const unsigned mbc = smem_u32(&mbC[0][0]);
    if (threadIdx.x == 0) {
#pragma unroll
        for (int q = 0; q < 8; q++) {
            asm volatile("mbarrier.init.shared.b64 [%0], %1;"
                         :: "r"(mbc + q * 8u), "r"(1u) : "memory");
            mbar_rearm(mbc + q * 8u, 512u);
        }
    }
    __syncthreads();
    asm volatile("barrier.cluster.arrive.aligned;" ::: "memory");
    asm volatile("barrier.cluster.wait.aligned;" ::: "memory");

    // gi prefetch for step 0
    float giR, giZ, giN;
    {
        const int t0 = dir ? (LL - 1) : 0;
        const float* gt = gi + (size_t)t0 * (3 * HH);
        giR = __ldg(gt + jh); giZ = __ldg(gt + HH + jh); giN = __ldg(gt + 2 * HH + jh);
    }

    unsigned parbits = 0u;
    for (int s = 0; s < LL; s++) {
        const int t = dir ? (LL - 1 - s) : s;
        float nxR = 0.f, nxZ = 0.f, nxN = 0.f;
        if (s + 1 < LL) {
            const int tn_ = dir ? (LL - 2 - s) : (s + 1);
            const float* gt = gi + (size_t)tn_ * (3 * HH);
            nxR = __ldg(gt + jh); nxZ = __ldg(gt + HH + jh); nxN = __ldg(gt + 2 * HH + jh);
        }
        const int sl = s & 1;
        const float* hp = hbuf[sl];
        const ull* hp64 = (const ull*)hp;
        ull aR0 = 0, aR1 = 0, aZ0 = 0, aZ1 = 0, aN0 = 0, aN1 = 0;
#pragma unroll
        for (int c = 0; c < 4; c++) {
            if (s > 0) {
                const unsigned idx = (unsigned)(c * 2 + sl);
                const unsigned ma = mbc + idx * 8u;
                mbar_wait(ma, (parbits >> idx) & 1u);
                parbits ^= (1u << idx);
                if (threadIdx.x == 0) mbar_rearm(ma, 512u);
            }
#pragma unroll
            for (int i = 2 * c; i < 2 * c + 2; i++) {
                ull hh = hp64[lane + 32 * i];
                ffma2(aR0, wt[0][i], hh); ffma2(aR1, wt[1][i], hh);
                ffma2(aZ0, wt[2][i], hh); ffma2(aZ1, wt[3][i], hh);
                ffma2(aN0, wt[4][i], hh); ffma2(aN1, wt[5][i], hh);
            }
        }
        // fold halves (k-even + k-odd) -> per-row scalars, re-pack (row j0, row j0+1)
        float2 r0 = unpk(aR0), r1 = unpk(aR1);
        float2 z0 = unpk(aZ0), z1 = unpk(aZ1);
        float2 n0 = unpk(aN0), n1 = unpk(aN1);
        ull aR = pack2(r0.x + r0.y, r1.x + r1.y);
        ull aZ = pack2(z0.x + z0.y, z1.x + z1.y);
        ull aN = pack2(n0.x + n0.y, n1.x + n1.y);
#pragma unroll
        for (int o = 16; o; o >>= 1) {
            ull tR = __shfl_xor_sync(0xffffffffu, aR, o);
            ull tZ = __shfl_xor_sync(0xffffffffu, aZ, o);
            ull tN = __shfl_xor_sync(0xffffffffu, aN, o);
            addx2(aR, tR); addx2(aZ, tZ); addx2(aN, tN);
        }
        float2 fR = unpk(aR), fZ = unpk(aZ), fN = unpk(aN);
        float aRs = half ? fR.y : fR.x;
        float aZs = half ? fZ.y : fZ.x;
        float aNs = half ? fN.y : fN.x;
        float rr = sigm_(giR + aRs + bRs);
        float zz = sigm_(giZ + aZs + bZs);
        float nn = tanh_(giN + rr * (aNs + bNs));
        float hprev = hp[jh];
        float hv = (1.f - zz) * nn + zz * hprev;
        float hov = __shfl_xor_sync(0xffffffffu, hv, 16);
        if (s + 1 < LL && lane < 16) {
            ull pairv = pack2(hv, hov);
            const int nsl = (s + 1) & 1;
            unsigned ldata = (nsl ? sb1 : sb0) + (unsigned)j0 * 4u;
            unsigned lmbar = mbc + (unsigned)((rank >> 2) * 2 + nsl) * 8u;
            unsigned rdata, rmbar;
            asm("mapa.shared::cluster.u32 %0, %1, %2;" : "=r"(rdata) : "r"(ldata), "r"(lane));
            asm("mapa.shared::cluster.u32 %0, %1, %2;" : "=r"(rmbar) : "r"(lmbar), "r"(lane));
            asm volatile("st.async.shared::cluster.mbarrier::complete_tx::bytes.b64 [%0], %1, [%2];"
                         :: "r"(rdata), "l"(pairv), "r"(rmbar) : "memory");
        }
        if (lane == 0) *(float2*)&outp[(size_t)t * (2 * HH) + j0] = make_float2(hv, hov);
        giR = nxR; giZ = nxZ; giN = nxN;
    }
    asm volatile("barrier.cluster.arrive.aligned;" ::: "memory");
    asm volatile("barrier.cluster.wait.aligned;" ::: "memory");
}

// ---------------- fallback GRU (R3, global-flag sync) ----------------
__global__ void __launch_bounds__(512, 1) gru_flags(
    const float* __restrict__ whh_f, const float* __restrict__ bhh_f,
    const float* __restrict__ whh_b, const float* __restrict__ bhh_b,
    float* __restrict__ out)
{
    const int dir = blockIdx.x >> 5, cta = blockIdx.x & 31;
    const int wrp = threadIdx.x >> 5, lane = threadIdx.x & 31;
    const int j = cta * 16 + wrp;
    const float* whh = dir ? whh_b : whh_f;
    const float* bhh = dir ? bhh_b : bhh_f;
    const float* gi  = dir ? g_gi_b : g_gi_f;

    float wr[16], wz[16], wn[16];
#pragma unroll
    for (int i = 0; i < 16; i++) {
        int k = lane + 32 * i;
        wr[i] = whh[(size_t)j * HH + k];
        wz[i] = whh[(size_t)(HH + j) * HH + k];
        wn[i] = whh[(size_t)(2 * HH + j) * HH + k];
    }
    const float bhr = bhh[j], bhz = bhh[HH + j], bhn = bhh[2 * HH + j];

    for (int s = 0; s < LL; s++) {
        const int t = dir ? (LL - 1 - s) : s;
        float giR = 0.f, giZ = 0.f, giN = 0.f;
        if (lane == 0) {
            const float* gt = gi + (size_t)t * (3 * HH);
            giR = __ldg(&gt[j]); giZ = __ldg(&gt[HH + j]); giN = __ldg(&gt[2 * HH + j]);
        }
        if (s > 0 && wrp == 0) {
            const unsigned tgt = (unsigned)s;
            while (__any_sync(0xffffffffu, ld_acq(&g_flag[dir][lane][0]) < tgt)) {}
        }
        __syncthreads();
        const float* hp = g_h[dir][s & 1];
        float* hn = g_h[dir][(s + 1) & 1];
        float aR = 0.f, aZ = 0.f, aN = 0.f;
#pragma unroll
        for (int i = 0; i < 16; i++) {
            float hv = __ldcg(&hp[lane + 32 * i]);
            aR = fmaf(wr[i], hv, aR);
            aZ = fmaf(wz[i], hv, aZ);
            aN = fmaf(wn[i], hv, aN);
        }
#pragma unroll
        for (int o = 16; o; o >>= 1) {
            aR += __shfl_xor_sync(0xffffffffu, aR, o);
            aZ += __shfl_xor_sync(0xffffffffu, aZ, o);
            aN += __shfl_xor_sync(0xffffffffu, aN, o);
        }
        if (lane == 0) {
            float r = sigm_(giR + aR + bhr);
            float z = sigm_(giZ + aZ + bhz);
            float n = tanh_(giN + r * (aN + bhn));
            float hprev = __ldcg(&hp[j]);
            float hnew = (1.f - z) * n + z * hprev;
            __stcg(&hn[j], hnew);
            out[(size_t)t * (2 * HH) + dir * HH + j] = hnew;
        }
        __syncthreads();
        if (threadIdx.x == 0) st_rel(&g_flag[dir][cta][0], (unsigned)(s + 1));
    }
}

// ---------------- launch ----------------
extern "C" void kernel_launch(void* const* d_in, const int* in_sizes, int n_in,
                              void* d_out, int out_size) {
    const float* v     = (const float*)d_in[0];
    const float* w1    = (const float*)d_in[1];
    const float* b1    = (const float*)d_in[2];
    const float* w2    = (const float*)d_in[3];
    const float* b2    = (const float*)d_in[4];
    const float* wih_f = (const float*)d_in[5];
    const float* whh_f = (const float*)d_in[6];
    const float* bih_f = (const float*)d_in[7];
    const float* bhh_f = (const float*)d_in[8];
    const float* wih_b = (const float*)d_in[9];
    const float* whh_b = (const float*)d_in[10];
    const float* bih_b = (const float*)d_in[11];
    const float* bhh_b = (const float*)d_in[12];
    float* out = (float*)d_out;

    cudaFuncSetAttribute((const void*)gru_cluster,
                         cudaFuncAttributeNonPortableClusterSizeAllowed, 1);
    cudaLaunchConfig_t cfg = {};
    cfg.gridDim = dim3(32, 1, 1);
    cfg.blockDim = dim3(512, 1, 1);
    cfg.dynamicSmemBytes = 0;
    cfg.stream = 0;
    cudaLaunchAttribute attrs[1];
    attrs[0].id = cudaLaunchAttributeClusterDimension;
    attrs[0].val.clusterDim = {16, 1, 1};
    cfg.attrs = attrs;
    cfg.numAttrs = 1;
    int nclus = 0;
    cudaError_t qe = cudaOccupancyMaxActiveClusters(&nclus, gru_cluster, &cfg);
    bool use_cluster = (qe == cudaSuccess && nclus >= 2);
    if (!use_cluster) cudaGetLastError();

    if (!use_cluster) init_zero<<<2, 1024>>>();
    gemm_head<<<dim3(24, 8, 4), 256>>>(v, w1, b1, w2, b2,
                                       wih_f, bih_f, wih_b, bih_b);  // idx 0
    attn_e<<<dim3(16, 32), dim3(32, 16)>>>(v);                        // idx 1
    softmax_rows<<<512, 512>>>();                                     // idx 2
    gemm_c32<<<dim3(8, 16), 256>>>(v);                                // idx 3
    gemm_tail<<<dim3(24, 8, 2), 256>>>(wih_f, wih_b);                 // idx 4

    if (use_cluster) {
        cudaError_t le = cudaLaunchKernelEx(&cfg, gru_cluster,
                                            whh_f, bhh_f, whh_b, bhh_b, out);  // idx 5
        if (le != cudaSuccess) {
            cudaGetLastError();
            init_zero<<<2, 1024>>>();
            gru_flags<<<64, 512>>>(whh_f, bhh_f, whh_b, bhh_b, out);
        }
    } else {
        gru_flags<<<64, 512>>>(whh_f, bhh_f, whh_b, bhh_b, out);
    }
}

// round 17
// speedup vs baseline: 1.0993x; 1.0218x over previous
#include <cuda_runtime.h>
#include <cuda_bf16.h>

#define LL 512
#define DD 512
#define HH 512

typedef unsigned long long ull;

// ---------------- device scratch ----------------
__device__ float g_u[LL * DD];
__device__ float g_w[LL * DD];
__device__ float g_e[LL * LL];
__device__ float g_a[LL * LL];
__device__ float g_c[LL * DD];
__device__ float g_gi_f[LL * 3 * HH];
__device__ float g_gi_b[LL * 3 * HH];
__device__ float g_h[2][2][HH];               // fallback: [dir][parity][h]
__device__ unsigned int g_flag[2][32][32];    // fallback: per-producer flag lines

__device__ __forceinline__ float sigm_(float x) {
    return __fdividef(1.f, 1.f + __expf(-x));
}
__device__ __forceinline__ float tanh_(float x) {
    return 1.f - __fdividef(2.f, __expf(x + x) + 1.f);
}
__device__ __forceinline__ unsigned int ld_acq(const unsigned int* p) {
    unsigned int v;
    asm volatile("ld.acquire.gpu.global.u32 %0, [%1];" : "=r"(v) : "l"(p) : "memory");
    return v;
}
__device__ __forceinline__ void st_rel(unsigned int* p, unsigned int v) {
    asm volatile("st.release.gpu.global.u32 [%0], %1;" :: "l"(p), "r"(v) : "memory");
}
__device__ __forceinline__ void ffma2(ull& d, ull a, ull b) {
    asm("fma.rn.f32x2 %0, %1, %2, %0;" : "+l"(d) : "l"(a), "l"(b));
}
__device__ __forceinline__ void addx2(ull& d, ull a) {
    asm("add.rn.f32x2 %0, %0, %1;" : "+l"(d) : "l"(a));
}
__device__ __forceinline__ ull packff(float x) {
    ull r; asm("mov.b64 %0, {%1, %1};" : "=l"(r) : "f"(x)); return r;
}
__device__ __forceinline__ ull pack2(float x, float y) {
    ull r; asm("mov.b64 %0, {%1, %2};" : "=l"(r) : "f"(x), "f"(y)); return r;
}
__device__ __forceinline__ float2 unpk(ull v) {
    float2 f; asm("mov.b64 {%0, %1}, %2;" : "=f"(f.x), "=f"(f.y) : "l"(v)); return f;
}
__device__ __forceinline__ unsigned smem_u32(const void* p) {
    unsigned a;
    asm("{ .reg .u64 t; cvta.to.shared.u64 t, %1; cvt.u32.u64 %0, t; }" : "=r"(a) : "l"(p));
    return a;
}
__device__ __forceinline__ unsigned ctarank_() {
    unsigned r; asm("mov.u32 %0, %%cluster_ctarank;" : "=r"(r)); return r;
}
__device__ __forceinline__ void mbar_wait(unsigned addr, unsigned parity) {
    asm volatile(
        "{\n\t"
        ".reg .pred P;\n\t"
        "WL_%=:\n\t"
        "mbarrier.try_wait.parity.acquire.cta.shared::cta.b64 P, [%0], %1, 0x989680;\n\t"
        "@!P bra WL_%=;\n\t"
        "}"
        :: "r"(addr), "r"(parity) : "memory");
}
__device__ __forceinline__ void mbar_rearm(unsigned addr, unsigned bytes) {
    asm volatile("mbarrier.arrive.expect_tx.shared.b64 _, [%0], %1;"
                 :: "r"(addr), "r"(bytes) : "memory");
}

// ---------------- init (fallback path only) ----------------
__global__ void init_zero() {
    int i = blockIdx.x * 1024 + threadIdx.x;
    if (i < 2048) ((unsigned int*)g_flag)[i] = 0u;
    if (i < 2048) ((float*)g_h)[i] = 0.f;
}

// ---------------- GEMM core (f32x2 packed, lda/ldb/accum generalized) ----------------
__device__ __forceinline__ void gemm_core(
    const float* __restrict__ A, int lda,
    const float* __restrict__ B, int ldb,
    const float* __restrict__ bias, float* __restrict__ C,
    int N, int Kloop, int transB, int accum, int m0, int n0)
{
    __shared__ __align__(16) float As[16][68];
    __shared__ __align__(16) float Bs[16][68];
    const int tid = threadIdx.x;
    const int tm = (tid >> 4) * 4, tn = (tid & 15) * 4;
    ull acc[4][2] = {};
    for (int k0 = 0; k0 < Kloop; k0 += 16) {
#pragma unroll
        for (int i = 0; i < 4; i++) {
            int e = tid + 256 * i;
            {
                int kk = e & 15, row = e >> 4;
                As[kk][row] = A[(size_t)(m0 + row) * lda + k0 + kk];
            }
            if (transB) {
                int kk = e & 15, row = e >> 4;
                Bs[kk][row] = B[(size_t)(n0 + row) * ldb + k0 + kk];
            } else {
                int n = e & 63, kk = e >> 6;
                Bs[kk][n] = B[(size_t)(k0 + kk) * ldb + n0 + n];
            }
        }
        __syncthreads();
#pragma unroll
        for (int kk = 0; kk < 16; kk++) {
            float4 a = *(const float4*)&As[kk][tm];
            const ull* bp = (const ull*)&Bs[kk][tn];
            ull b01 = bp[0], b23 = bp[1];
            ull a0 = packff(a.x), a1 = packff(a.y), a2 = packff(a.z), a3 = packff(a.w);
            ffma2(acc[0][0], a0, b01); ffma2(acc[0][1], a0, b23);
            ffma2(acc[1][0], a1, b01); ffma2(acc[1][1], a1, b23);
            ffma2(acc[2][0], a2, b01); ffma2(acc[2][1], a2, b23);
            ffma2(acc[3][0], a3, b01); ffma2(acc[3][1], a3, b23);
        }
        __syncthreads();
    }
#pragma unroll
    for (int i = 0; i < 4; i++) {
        float2 c01 = unpk(acc[i][0]), c23 = unpk(acc[i][1]);
        float* cp = C + (size_t)(m0 + tm + i) * N + n0 + tn;
        float b0 = 0.f, b1 = 0.f, b2 = 0.f, b3 = 0.f;
        if (bias) { b0 = bias[n0+tn]; b1 = bias[n0+tn+1]; b2 = bias[n0+tn+2]; b3 = bias[n0+tn+3]; }
        if (accum) { b0 += cp[0]; b1 += cp[1]; b2 += cp[2]; b3 += cp[3]; }
        cp[0] = c01.x + b0; cp[1] = c01.y + b1; cp[2] = c23.x + b2; cp[3] = c23.y + b3;
    }
}

// head: z=0 -> u, z=1 -> w (8x8 blocks), z=2/3 -> gi v-half (24x8)
__global__ void gemm_head(const float* __restrict__ v,
                          const float* __restrict__ w1, const float* __restrict__ b1,
                          const float* __restrict__ w2, const float* __restrict__ b2,
                          const float* __restrict__ wih_f, const float* __restrict__ bih_f,
                          const float* __restrict__ wih_b, const float* __restrict__ bih_b) {
    const int z = blockIdx.z;
    const int m0 = blockIdx.y * 64, n0 = blockIdx.x * 64;
    if (z < 2) {
        if (blockIdx.x >= 8) return;
        if (z == 0) gemm_core(v, 512, w1, 512, b1, g_u, 512, 512, 1, 0, m0, n0);
        else        gemm_core(v, 512, w2, 512, b2, g_w, 512, 512, 1, 0, m0, n0);
    } else {
        if (z == 2) gemm_core(v, 512, wih_f, 1024, bih_f, g_gi_f, 1536, 512, 1, 0, m0, n0);
        else        gemm_core(v, 512, wih_b, 1024, bih_b, g_gi_b, 1536, 512, 1, 0, m0, n0);
    }
}
// c = a @ v with 32x32 tiles (256 CTAs -> 1-2 resident CTAs/SM, hides LDG latency)
__global__ void gemm_c3232(const float* __restrict__ v) {
    __shared__ __align__(16) float As[16][36];
    __shared__ __align__(16) float Bs[16][36];
    const int tid = threadIdx.x;
    const int m0 = blockIdx.y * 32, n0 = blockIdx.x * 32;
    const int tm = (tid >> 4) * 2, tn = (tid & 15) * 2;
    ull acc[2] = {};
    ull acc1[2] = {};
    for (int k0 = 0; k0 < 512; k0 += 16) {
        {   // A tile: 32 rows x 16 k = 512 elems, 2 per thread
#pragma unroll
            for (int i = 0; i < 2; i++) {
                int e = tid + 256 * i;
                int kk = e & 15, row = e >> 4;
                As[kk][row] = g_a[(size_t)(m0 + row) * 512 + k0 + kk];
            }
        }
        {   // B tile: 16 k x 32 n = 512 elems, 2 per thread
#pragma unroll
            for (int i = 0; i < 2; i++) {
                int e = tid + 256 * i;
                int n = e & 31, kk = e >> 5;
                Bs[kk][n] = v[(size_t)(k0 + kk) * 512 + n0 + n];
            }
        }
        __syncthreads();
#pragma unroll
        for (int kk = 0; kk < 16; kk++) {
            float2 a2 = *(const float2*)&As[kk][tm];
            ull b01 = *(const ull*)&Bs[kk][tn];
            ull a0 = packff(a2.x), a1 = packff(a2.y);
            ffma2(acc[0], a0, b01);
            ffma2(acc1[0], a1, b01);
        }
        __syncthreads();
    }
    {
        float2 c0 = unpk(acc[0]), c1 = unpk(acc1[0]);
        float* cp0 = g_c + (size_t)(m0 + tm) * 512 + n0 + tn;
        float* cp1 = g_c + (size_t)(m0 + tm + 1) * 512 + n0 + tn;
        cp0[0] = c0.x; cp0[1] = c0.y;
        cp1[0] = c1.x; cp1[1] = c1.y;
    }
}
__global__ void gemm_tail(const float* __restrict__ wih_f, const float* __restrict__ wih_b) {
    const int m0 = blockIdx.y * 64, n0 = blockIdx.x * 64;
    if (blockIdx.z == 0) gemm_core(g_c, 512, wih_f + 512, 1024, nullptr, g_gi_f, 1536, 512, 1, 1, m0, n0);
    else                 gemm_core(g_c, 512, wih_b + 512, 1024, nullptr, g_gi_b, 1536, 512, 1, 1, m0, n0);
}

// ---------------- attn e ----------------
__global__ void attn_e(const float* __restrict__ v) {
    __shared__ float us[32][33], vs[32][33], ws[16][33];
    const int tx = threadIdx.x, ty = threadIdx.y;
    const int j0 = blockIdx.x * 32, t0 = blockIdx.y * 16;
    float acc = 0.f;
    for (int d0 = 0; d0 < DD; d0 += 32) {
        us[ty][tx]      = g_u[(j0 + ty) * DD + d0 + tx];
        us[ty + 16][tx] = g_u[(j0 + ty + 16) * DD + d0 + tx];
        vs[ty][tx]      = v[(j0 + ty) * DD + d0 + tx];
        vs[ty + 16][tx] = v[(j0 + ty + 16) * DD + d0 + tx];
        ws[ty][tx]      = g_w[(t0 + ty) * DD + d0 + tx];
        __syncthreads();
#pragma unroll
        for (int dd = 0; dd < 32; dd++) {
            float x = us[tx][dd] + ws[ty][dd];
            float th = 1.f - __fdividef(2.f, __expf(x + x) + 1.f);
            acc = fmaf(th, vs[tx][dd], acc);
        }
        __syncthreads();
    }
    g_e[(t0 + ty) * LL + j0 + tx] = acc;
}

// ---------------- softmax rows ----------------
__global__ void softmax_rows() {
    __shared__ float red[16];
    __shared__ float bval;
    const int t = blockIdx.x, tid = threadIdx.x, w = tid >> 5, l = tid & 31;
    float x = g_e[t * LL + tid];
    float m = x;
#pragma unroll
    for (int o = 16; o; o >>= 1) m = fmaxf(m, __shfl_xor_sync(~0u, m, o));
    if (l == 0) red[w] = m;
    __syncthreads();
    if (tid == 0) {
        float mm = red[0];
#pragma unroll
        for (int i = 1; i < 16; i++) mm = fmaxf(mm, red[i]);
        bval = mm;
    }
    __syncthreads();
    float p = __expf(x - bval);
    float s = p;
#pragma unroll
    for (int o = 16; o; o >>= 1) s += __shfl_xor_sync(~0u, s, o);
    if (l == 0) red[w] = s;
    __syncthreads();
    if (tid == 0) {
        float ss = red[0];
#pragma unroll
        for (int i = 1; i < 16; i++) ss += red[i];
        bval = ss;
    }
    __syncthreads();
    g_a[t * LL + tid] = __fdividef(p, bval);
}

// ======== GRU scan: 16-CTA cluster, 4-chunk st.async publish + half-warp gates ========
// (exact R13 structure: best measured 799.2 us)
__global__ void __launch_bounds__(512, 1) gru_cluster(
    const float* __restrict__ whh_f, const float* __restrict__ bhh_f,
    const float* __restrict__ whh_b, const float* __restrict__ bhh_b,
    float* __restrict__ out)
{
    __shared__ __align__(16) float hbuf[2][HH];
    __shared__ __align__(8) ull mbC[4][2];
    const int dir = blockIdx.x >> 4;
    const int wrp = threadIdx.x >> 5, lane = threadIdx.x & 31;
    const unsigned rank = ctarank_();
    const int j0 = (int)rank * 32 + wrp * 2;
    const int half = lane >> 4;          // 0 -> h_even (j0), 1 -> h_odd (j0+1)
    const int jh = j0 + half;
    const float* whh = dir ? whh_b : whh_f;
    const float* bhh = dir ? bhh_b : bhh_f;
    const float* gi  = dir ? g_gi_b : g_gi_f;
    float* outp = out + dir * HH;

    // weights packed for k = lane + 32*i, pair = (row j0, row j0+1)
    ull wt[3][16];
#pragma unroll
    for (int g = 0; g < 3; g++) {
        const float* r0 = whh + ((size_t)(g * HH + j0)) * HH;
        const float* r1 = r0 + HH;
#pragma unroll
        for (int i = 0; i < 16; i++) {
            int k = lane + 32 * i;
            wt[g][i] = pack2(r0[k], r1[k]);
        }
    }
    const float bRs = bhh[jh], bZs = bhh[HH + jh], bNs = bhh[2 * HH + jh];

    for (int i = threadIdx.x; i < HH; i += 512) hbuf[0][i] = 0.f;
    const unsigned sb0 = smem_u32(&hbuf[0][0]);
    const unsigned sb1 = smem_u32(&hbuf[1][0]);
    const unsigned mbc = smem_u32(&mbC[0][0]);
    if (threadIdx.x == 0) {
#pragma unroll
        for (int q = 0; q < 8; q++) {
            asm volatile("mbarrier.init.shared.b64 [%0], %1;"
                         :: "r"(mbc + q * 8u), "r"(1u) : "memory");
            mbar_rearm(mbc + q * 8u, 512u);
        }
    }
    __syncthreads();
    asm volatile("barrier.cluster.arrive.aligned;" ::: "memory");
    asm volatile("barrier.cluster.wait.aligned;" ::: "memory");

    // gi prefetch for step 0 (each lane loads its half's values)
    float giR, giZ, giN;
    {
        const int t0 = dir ? (LL - 1) : 0;
        const float* gt = gi + (size_t)t0 * (3 * HH);
        giR = __ldg(gt + jh); giZ = __ldg(gt + HH + jh); giN = __ldg(gt + 2 * HH + jh);
    }

    unsigned parbits = 0u;   // bit (c*2+sl)
    for (int s = 0; s < LL; s++) {
        const int t = dir ? (LL - 1 - s) : s;
        // prefetch gi for step s+1
        float nxR = 0.f, nxZ = 0.f, nxN = 0.f;
        if (s + 1 < LL) {
            const int tn_ = dir ? (LL - 2 - s) : (s + 1);
            const float* gt = gi + (size_t)tn_ * (3 * HH);
            nxR = __ldg(gt + jh); nxZ = __ldg(gt + HH + jh); nxN = __ldg(gt + 2 * HH + jh);
        }
        const int sl = s & 1;
        const float* hp = hbuf[sl];
        ull aR = 0, aZ = 0, aN = 0;
#pragma unroll
        for (int c = 0; c < 4; c++) {
            if (s > 0) {
                const unsigned idx = (unsigned)(c * 2 + sl);
                const unsigned ma = mbc + idx * 8u;
                mbar_wait(ma, (parbits >> idx) & 1u);
                parbits ^= (1u << idx);
                if (threadIdx.x == 0) mbar_rearm(ma, 512u);
            }
#pragma unroll
            for (int i = 4 * c; i < 4 * c + 4; i++) {
                ull hh = packff(hp[lane + 32 * i]);
                ffma2(aR, wt[0][i], hh); ffma2(aZ, wt[1][i], hh); ffma2(aN, wt[2][i], hh);
            }
        }
#pragma unroll
        for (int o = 16; o; o >>= 1) {
            ull tR = __shfl_xor_sync(0xffffffffu, aR, o);
            ull tZ = __shfl_xor_sync(0xffffffffu, aZ, o);
            ull tN = __shfl_xor_sync(0xffffffffu, aN, o);
            addx2(aR, tR); addx2(aZ, tZ); addx2(aN, tN);
        }
        float2 fR = unpk(aR), fZ = unpk(aZ), fN = unpk(aN);
        // half-warp gates: low lanes h_even, high lanes h_odd
        float aRs = half ? fR.y : fR.x;
        float aZs = half ? fZ.y : fZ.x;
        float aNs = half ? fN.y : fN.x;
        float rr = sigm_(giR + aRs + bRs);
        float zz = sigm_(giZ + aZs + bZs);
        float nn = tanh_(giN + rr * (aNs + bNs));
        float hprev = hp[jh];
        float hv = (1.f - zz) * nn + zz * hprev;
        float hov = __shfl_xor_sync(0xffffffffu, hv, 16);   // partner half's value
        if (s + 1 < LL && lane < 16) {
            ull pairv = pack2(hv, hov);                      // (h_even, h_odd)
            const int nsl = (s + 1) & 1;
            unsigned ldata = (nsl ? sb1 : sb0) + (unsigned)j0 * 4u;
            unsigned lmbar = mbc + (unsigned)((rank >> 2) * 2 + nsl) * 8u;
            unsigned rdata, rmbar;
            asm("mapa.shared::cluster.u32 %0, %1, %2;" : "=r"(rdata) : "r"(ldata), "r"(lane));
            asm("mapa.shared::cluster.u32 %0, %1, %2;" : "=r"(rmbar) : "r"(lmbar), "r"(lane));
            asm volatile("st.async.shared::cluster.mbarrier::complete_tx::bytes.b64 [%0], %1, [%2];"
                         :: "r"(rdata), "l"(pairv), "r"(rmbar) : "memory");
        }
        if (lane == 0) *(float2*)&outp[(size_t)t * (2 * HH) + j0] = make_float2(hv, hov);
        giR = nxR; giZ = nxZ; giN = nxN;
    }
    asm volatile("barrier.cluster.arrive.aligned;" ::: "memory");
    asm volatile("barrier.cluster.wait.aligned;" ::: "memory");
}

// ---------------- fallback GRU (R3, global-flag sync) ----------------
__global__ void __launch_bounds__(512, 1) gru_flags(
    const float* __restrict__ whh_f, const float* __restrict__ bhh_f,
    const float* __restrict__ whh_b, const float* __restrict__ bhh_b,
    float* __restrict__ out)
{
    const int dir = blockIdx.x >> 5, cta = blockIdx.x & 31;
    const int wrp = threadIdx.x >> 5, lane = threadIdx.x & 31;
    const int j = cta * 16 + wrp;
    const float* whh = dir ? whh_b : whh_f;
    const float* bhh = dir ? bhh_b : bhh_f;
    const float* gi  = dir ? g_gi_b : g_gi_f;

    float wr[16], wz[16], wn[16];
#pragma unroll
    for (int i = 0; i < 16; i++) {
        int k = lane + 32 * i;
        wr[i] = whh[(size_t)j * HH + k];
        wz[i] = whh[(size_t)(HH + j) * HH + k];
        wn[i] = whh[(size_t)(2 * HH + j) * HH + k];
    }
    const float bhr = bhh[j], bhz = bhh[HH + j], bhn = bhh[2 * HH + j];

    for (int s = 0; s < LL; s++) {
        const int t = dir ? (LL - 1 - s) : s;
        float giR = 0.f, giZ = 0.f, giN = 0.f;
        if (lane == 0) {
            const float* gt = gi + (size_t)t * (3 * HH);
            giR = __ldg(&gt[j]); giZ = __ldg(&gt[HH + j]); giN = __ldg(&gt[2 * HH + j]);
        }
        if (s > 0 && wrp == 0) {
            const unsigned tgt = (unsigned)s;
            while (__any_sync(0xffffffffu, ld_acq(&g_flag[dir][lane][0]) < tgt)) {}
        }
        __syncthreads();
        const float* hp = g_h[dir][s & 1];
        float* hn = g_h[dir][(s + 1) & 1];
        float aR = 0.f, aZ = 0.f, aN = 0.f;
#pragma unroll
        for (int i = 0; i < 16; i++) {
            float hv = __ldcg(&hp[lane + 32 * i]);
            aR = fmaf(wr[i], hv, aR);
            aZ = fmaf(wz[i], hv, aZ);
            aN = fmaf(wn[i], hv, aN);
        }
#pragma unroll
        for (int o = 16; o; o >>= 1) {
            aR += __shfl_xor_sync(0xffffffffu, aR, o);
            aZ += __shfl_xor_sync(0xffffffffu, aZ, o);
            aN += __shfl_xor_sync(0xffffffffu, aN, o);
        }
        if (lane == 0) {
            float r = sigm_(giR + aR + bhr);
            float z = sigm_(giZ + aZ + bhz);
            float n = tanh_(giN + r * (aN + bhn));
            float hprev = __ldcg(&hp[j]);
            float hnew = (1.f - z) * n + z * hprev;
            __stcg(&hn[j], hnew);
            out[(size_t)t * (2 * HH) + dir * HH + j] = hnew;
        }
        __syncthreads();
        if (threadIdx.x == 0) st_rel(&g_flag[dir][cta][0], (unsigned)(s + 1));
    }
}

// ---------------- launch ----------------
extern "C" void kernel_launch(void* const* d_in, const int* in_sizes, int n_in,
                              void* d_out, int out_size) {
    const float* v     = (const float*)d_in[0];
    const float* w1    = (const float*)d_in[1];
    const float* b1    = (const float*)d_in[2];
    const float* w2    = (const float*)d_in[3];
    const float* b2    = (const float*)d_in[4];
    const float* wih_f = (const float*)d_in[5];
    const float* whh_f = (const float*)d_in[6];
    const float* bih_f = (const float*)d_in[7];
    const float* bhh_f = (const float*)d_in[8];
    const float* wih_b = (const float*)d_in[9];
    const float* whh_b = (const float*)d_in[10];
    const float* bih_b = (const float*)d_in[11];
    const float* bhh_b = (const float*)d_in[12];
    float* out = (float*)d_out;

    cudaFuncSetAttribute((const void*)gru_cluster,
                         cudaFuncAttributeNonPortableClusterSizeAllowed, 1);
    cudaLaunchConfig_t cfg = {};
    cfg.gridDim = dim3(32, 1, 1);
    cfg.blockDim = dim3(512, 1, 1);
    cfg.dynamicSmemBytes = 0;
    cfg.stream = 0;
    cudaLaunchAttribute attrs[1];
    attrs[0].id = cudaLaunchAttributeClusterDimension;
    attrs[0].val.clusterDim = {16, 1, 1};
    cfg.attrs = attrs;
    cfg.numAttrs = 1;
    int nclus = 0;
    cudaError_t qe = cudaOccupancyMaxActiveClusters(&nclus, gru_cluster, &cfg);
    bool use_cluster = (qe == cudaSuccess && nclus >= 2);
    if (!use_cluster) cudaGetLastError();

    if (!use_cluster) init_zero<<<2, 1024>>>();
    gemm_head<<<dim3(24, 8, 4), 256>>>(v, w1, b1, w2, b2,
                                       wih_f, bih_f, wih_b, bih_b);  // idx 0
    attn_e<<<dim3(16, 32), dim3(32, 16)>>>(v);                        // idx 1
    softmax_rows<<<512, 512>>>();                                     // idx 2
    gemm_c3232<<<dim3(16, 16), 256>>>(v);                             // idx 3
    gemm_tail<<<dim3(24, 8, 2), 256>>>(wih_f, wih_b);                 // idx 4

    if (use_cluster) {
        cudaError_t le = cudaLaunchKernelEx(&cfg, gru_cluster,
                                            whh_f, bhh_f, whh_b, bhh_b, out);  // idx 5
        if (le != cudaSuccess) {
            cudaGetLastError();
            init_zero<<<2, 1024>>>();
            gru_flags<<<64, 512>>>(whh_f, bhh_f, whh_b, bhh_b, out);
        }
    } else {
        gru_flags<<<64, 512>>>(whh_f, bhh_f, whh_b, bhh_b, out);
    }
}